// round 11
// baseline (speedup 1.0000x reference)
#include <cuda_runtime.h>
#include <math.h>

// Problem constants (shapes fixed by the dataset)
#define NN 50000
#define NE 800000
#define D0 64   // x features
#define D1 96   // hidden
#define D2 64   // out

#define GRID 740    // 5 blocks/SM * 148 SMs — fully balanced persistent grid
#define NT   256    // threads per block

// ---------------- scratch (device globals: no allocation allowed) ----------
__device__ int      g_is64;
__device__ int      g_csr[NE];
__device__ int      g_cnt[NN];
__device__ int      g_row[NN + 1];
__device__ int      g_cur[NN];
__device__ float    g_dis[NN];
__device__ int      g_bsum[GRID];
__device__ int      g_bpre[GRID];
__device__ unsigned g_barrier_ctr;   // monotonic across launches (replay-safe)
__device__ float    g_h1 [NN * D1];  // x@W1 (UNSCALED)
__device__ float    g_h  [NN * D1];  // relu(layer1)
__device__ float    g_hs2[NN * D2];  // (h@W2)*dis[row]

__device__ __forceinline__ float act_relu(float v)    { return fmaxf(v, 0.0f); }
__device__ __forceinline__ float act_sigmoid(float v) { return 1.0f / (1.0f + expf(-v)); }

// ---------------- software grid barrier ------------------------------------
// Monotonic counter, never reset: each barrier consumes exactly GRID arrivals.
__device__ __forceinline__ void gbar() {
    __threadfence();
    __syncthreads();
    if (threadIdx.x == 0) {
        unsigned old = atomicAdd(&g_barrier_ctr, 1u);
        unsigned target = (old / GRID) * GRID + GRID;
        while ((int)(*(volatile unsigned*)&g_barrier_ctr - target) < 0)
            __nanosleep(64);
        __threadfence();
    }
    __syncthreads();
}

// ---------------- GEMM phase (crossbar-optimized) --------------------------
// HS[row][c] = (SCALE ? dis[row] : 1) * sum_k X[row][k]*W[k][c].
// X staged TRANSPOSED: sXsT[k*32 + r] for a 32-row tile -> per k one
// LDS.128 broadcast gives a warp its 4 row-values (1 wavefront, was 4).
// W fragment: lane owns CPT consecutive cols -> vector LDS (same bytes,
// fewer instructions). Per k per warp: gemm1 4 wf (was 7), gemm2 3 (was 6).
template <int IN, int OUT, bool SCALE>
__device__ void gemm_phase(const float* __restrict__ X, const float* __restrict__ W,
                           float* __restrict__ HS, float* sWs, float* sXsT,
                           int tile0, int tstride) {
    constexpr int K4     = IN / 4;
    constexpr int CPT    = (OUT == 96) ? 4 : 2;   // cols per thread
    constexpr int ALANES = OUT / CPT;             // 24 (OUT=96) or 32 (OUT=64)
    int t = threadIdx.x;
    // stage W once (float4, row-major)
    for (int i = t; i < IN * OUT / 4; i += NT)
        ((float4*)sWs)[i] = ((const float4*)W)[i];

    int w = t >> 5, lane = t & 31;
    int rbase = w * 4;
    int cl = (lane < ALANES) ? lane : (ALANES - 1);  // clamp: idle lanes read safely
    int ntile = (NN + 31) / 32;

    for (int tile = tile0; tile < ntile; tile += tstride) {
        __syncthreads();   // Ws ready (iter 0) / prior readers done with XsT
        int row0 = tile * 32;
        // stage X transposed: i enumerates (k4, r); consecutive lanes ->
        // consecutive r -> conflict-free STS. LDG is strided (row-major X)
        // but X is read exactly once overall — sector overfetch is cheap.
        for (int i = t; i < 32 * K4; i += NT) {
            int k4 = i >> 5, r = i & 31;
            int gr = row0 + r;
            float4 v = (gr < NN) ? ((const float4*)X)[gr * K4 + k4]
                                 : make_float4(0.f, 0.f, 0.f, 0.f);
            sXsT[(4 * k4 + 0) * 32 + r] = v.x;
            sXsT[(4 * k4 + 1) * 32 + r] = v.y;
            sXsT[(4 * k4 + 2) * 32 + r] = v.z;
            sXsT[(4 * k4 + 3) * 32 + r] = v.w;
        }
        __syncthreads();

        float acc[4][CPT];
#pragma unroll
        for (int r = 0; r < 4; r++)
#pragma unroll
            for (int c = 0; c < CPT; c++) acc[r][c] = 0.0f;

#pragma unroll
        for (int k = 0; k < IN; k++) {
            // 4 row-values for this warp: one 16B broadcast
            float4 xv = *(const float4*)&sXsT[k * 32 + rbase];
            float wv[CPT];
            if (CPT == 4) {
                float4 wq = *(const float4*)&sWs[k * OUT + 4 * cl];
                wv[0] = wq.x; wv[1] = wq.y; wv[2] = wq.z; wv[3] = wq.w;
            } else {
                float2 wq = *(const float2*)&sWs[k * OUT + 2 * cl];
                wv[0] = wq.x; wv[1] = wq.y;
            }
            const float xr[4] = {xv.x, xv.y, xv.z, xv.w};
#pragma unroll
            for (int r = 0; r < 4; r++)
#pragma unroll
                for (int c = 0; c < CPT; c++)
                    acc[r][c] = fmaf(xr[r], wv[c], acc[r][c]);
        }

        if (lane < ALANES) {
#pragma unroll
            for (int r = 0; r < 4; r++) {
                int gr = row0 + rbase + r;
                if (gr < NN) {
                    float d = SCALE ? g_dis[gr] : 1.0f;
                    if (CPT == 4) {
                        float4 o;
                        o.x = SCALE ? acc[r][0] * d : acc[r][0];
                        o.y = SCALE ? acc[r][1] * d : acc[r][1];
                        o.z = SCALE ? acc[r][2] * d : acc[r][2];
                        o.w = SCALE ? acc[r][3] * d : acc[r][3];
                        ((float4*)&HS[gr * OUT])[cl] = o;
                    } else {
                        float2 o;
                        o.x = SCALE ? acc[r][0] * d : acc[r][0];
                        o.y = SCALE ? acc[r][1] * d : acc[r][1];
                        ((float2*)&HS[gr * OUT])[cl] = o;
                    }
                }
            }
        }
    }
}

// ---------------- Aggregation phases ---------------------------------------
// Layer 1 (F=96, relu, SRC-SCALED): H is UNSCALED x@W1; apply dis[src] per
// edge and dis[node] on the self term / final combine:
//   out[i] = relu( dis_i * ( dis_i*H[i] + sum_e dis_src*H[src] ) + b )
__device__ void agg1_phase(const float* __restrict__ HS, const float* __restrict__ b,
                           float* __restrict__ OUT) {
    constexpr int F = D1, C4 = F / 4;          // 24 float4 cols; lanes 0..23
    int warp0 = (blockIdx.x * NT + threadIdx.x) >> 5;
    int lane  = threadIdx.x & 31;
    constexpr int WSTRIDE = GRID * NT / 32;

    const float4* H4 = (const float4*)HS;
    bool on = lane < C4;

    for (int node = warp0; node < NN; node += WSTRIDE) {
        int beg = g_row[node], end = g_row[node + 1];
        float di = g_dis[node];
        float4 acc = make_float4(0.f, 0.f, 0.f, 0.f);
        if (on) {
            float4 hv = H4[node * C4 + lane];          // self loop (scaled by di)
            acc.x = hv.x * di; acc.y = hv.y * di;
            acc.z = hv.z * di; acc.w = hv.w * di;
        }

        int j = beg;
        for (; j + 4 <= end; j += 4) {
            int s0 = g_csr[j + 0], s1 = g_csr[j + 1];
            int s2 = g_csr[j + 2], s3 = g_csr[j + 3];
            float d0 = g_dis[s0], d1 = g_dis[s1], d2 = g_dis[s2], d3 = g_dis[s3];
            if (on) {
                float4 v0 = H4[s0 * C4 + lane];
                float4 v1 = H4[s1 * C4 + lane];
                float4 v2 = H4[s2 * C4 + lane];
                float4 v3 = H4[s3 * C4 + lane];
                acc.x = fmaf(v0.x, d0, fmaf(v1.x, d1, fmaf(v2.x, d2, fmaf(v3.x, d3, acc.x))));
                acc.y = fmaf(v0.y, d0, fmaf(v1.y, d1, fmaf(v2.y, d2, fmaf(v3.y, d3, acc.y))));
                acc.z = fmaf(v0.z, d0, fmaf(v1.z, d1, fmaf(v2.z, d2, fmaf(v3.z, d3, acc.z))));
                acc.w = fmaf(v0.w, d0, fmaf(v1.w, d1, fmaf(v2.w, d2, fmaf(v3.w, d3, acc.w))));
            }
        }
        for (; j < end; j++) {
            int s0 = g_csr[j];
            float d0 = g_dis[s0];
            if (on) {
                float4 v = H4[s0 * C4 + lane];
                acc.x = fmaf(v.x, d0, acc.x); acc.y = fmaf(v.y, d0, acc.y);
                acc.z = fmaf(v.z, d0, acc.z); acc.w = fmaf(v.w, d0, acc.w);
            }
        }
        if (on) {
            float4 bb = ((const float4*)b)[lane];
            float4 o;
            o.x = act_relu(fmaf(di, acc.x, bb.x));
            o.y = act_relu(fmaf(di, acc.y, bb.y));
            o.z = act_relu(fmaf(di, acc.z, bb.z));
            o.w = act_relu(fmaf(di, acc.w, bb.w));
            ((float4*)OUT)[node * C4 + lane] = o;
        }
    }
}

// Layer 2 (F=64, sigmoid): HS is PRE-SCALED (h@W2)*dis.
//   out[i] = sigmoid( dis_i * ( HS[i] + sum_e HS[src] ) + b )
__device__ void agg2_phase(const float* __restrict__ HS, const float* __restrict__ b,
                           float* __restrict__ OUT) {
    constexpr int F = D2, C2 = F / 2;          // 32 float2 cols, all lanes
    int warp0 = (blockIdx.x * NT + threadIdx.x) >> 5;
    int lane  = threadIdx.x & 31;
    constexpr int WSTRIDE = GRID * NT / 32;

    const float2* H2 = (const float2*)HS;

    for (int node = warp0; node < NN; node += WSTRIDE) {
        int beg = g_row[node], end = g_row[node + 1];
        float2 acc = H2[node * C2 + lane];  // self loop

        int j = beg;
        for (; j + 4 <= end; j += 4) {
            int s0 = g_csr[j + 0], s1 = g_csr[j + 1];
            int s2 = g_csr[j + 2], s3 = g_csr[j + 3];
            float2 v0 = H2[s0 * C2 + lane];
            float2 v1 = H2[s1 * C2 + lane];
            float2 v2 = H2[s2 * C2 + lane];
            float2 v3 = H2[s3 * C2 + lane];
            acc.x += (v0.x + v1.x) + (v2.x + v3.x);
            acc.y += (v0.y + v1.y) + (v2.y + v3.y);
        }
        for (; j < end; j++) {
            int s0 = g_csr[j];
            float2 v = H2[s0 * C2 + lane];
            acc.x += v.x; acc.y += v.y;
        }
        float d = g_dis[node];
        float2 bb = ((const float2*)b)[lane];
        float2 o;
        o.x = act_sigmoid(fmaf(d, acc.x, bb.x));
        o.y = act_sigmoid(fmaf(d, acc.y, bb.y));
        ((float2*)OUT)[node * C2 + lane] = o;
    }
}

// ---------------- the single fused persistent kernel -----------------------
// smem: sWs 24KB + sXsT 12KB + scan 1KB -> ~37.3KB; 5 blocks/SM (<=51 regs).
__global__ void __launch_bounds__(NT, 5)
k_fused(const float* __restrict__ x, const void* __restrict__ ep,
        const float* __restrict__ W1, const float* __restrict__ b1,
        const float* __restrict__ W2, const float* __restrict__ b2,
        float* __restrict__ out) {
    __shared__ __align__(16) float sWs[D1 * D2 > D0 * D1 ? D1 * D2 : D0 * D1];
    __shared__ __align__(16) float sXsT[D1 * 32];   // max IN=96, 32-row tile
    __shared__ int   sScan[NT];
    __shared__ int   s_nz;

    int t   = threadIdx.x;
    int blk = blockIdx.x;
    int gid = blk * NT + t;

    // ---- P0: zero histogram; block 0 detects edge dtype.
    // Values in [0,50000): little-endian int64 => odd 32-bit words of the
    // first 1024 entries are all 0; int32 => they are random edge ids.
    if (gid < NN) g_cnt[gid] = 0;
    if (blk == 0) {
        const int* e = (const int*)ep;
        int local = 0;
#pragma unroll
        for (int q = 0; q < 4; q++) local |= e[2 * (t * 4 + q) + 1];
        if (t == 0) s_nz = 0;
        __syncthreads();
        if (local) atomicOr(&s_nz, 1);
        __syncthreads();
        if (t == 0) g_is64 = (s_nz == 0) ? 1 : 0;
    }
    gbar();
    int is64 = __ldcg(&g_is64);

    // ---- P1: in-degree histogram + GEMM1 (unscaled) in the SAME phase.
    if (is64) {
        const longlong2* p = (const longlong2*)ep;
        for (int i = gid; i < NE / 2; i += GRID * NT) {
            longlong2 dd = p[NE / 2 + i];
            atomicAdd(&g_cnt[(int)dd.x], 1);
            atomicAdd(&g_cnt[(int)dd.y], 1);
        }
    } else {
        const int2* p = (const int2*)ep;
        for (int i = gid; i < NE / 2; i += GRID * NT) {
            int2 dd = p[NE / 2 + i];
            atomicAdd(&g_cnt[dd.x], 1);
            atomicAdd(&g_cnt[dd.y], 1);
        }
    }
    gemm_phase<D0, D1, false>(x, W1, g_h1, sWs, sXsT, blk, GRID);
    gbar();

    // ---- P2a: block-local inclusive scan of counts (one node per thread)
    int c = (gid < NN) ? __ldcg(&g_cnt[gid]) : 0;
    sScan[t] = c;
    __syncthreads();
#pragma unroll
    for (int off = 1; off < NT; off <<= 1) {
        int v = sScan[t];
        int a = (t >= off) ? sScan[t - off] : 0;
        __syncthreads();
        sScan[t] = v + a;
        __syncthreads();
    }
    int incl = sScan[t];
    if (t == NT - 1) g_bsum[blk] = incl;
    gbar();

    // ---- P2b: block 0 scans the GRID block totals (PB per thread)
    if (blk == 0) {
        constexpr int PB = (GRID + NT - 1) / NT;   // 3
        int loc[PB];
        int s = 0;
#pragma unroll
        for (int q = 0; q < PB; q++) {
            int idx = t * PB + q;
            loc[q] = (idx < GRID) ? __ldcg(&g_bsum[idx]) : 0;
            s += loc[q];
        }
        sScan[t] = s;
        __syncthreads();
#pragma unroll
        for (int off = 1; off < NT; off <<= 1) {
            int v = sScan[t];
            int ad = (t >= off) ? sScan[t - off] : 0;
            __syncthreads();
            sScan[t] = v + ad;
            __syncthreads();
        }
        int run = sScan[t] - s;   // exclusive prefix for this thread's chunk
#pragma unroll
        for (int q = 0; q < PB; q++) {
            int idx = t * PB + q;
            if (idx < GRID) { g_bpre[idx] = run; run += loc[q]; }
        }
    }
    gbar();

    // ---- P2c: write row/cur/dis
    if (gid < NN) {
        int base = __ldcg(&g_bpre[blk]);
        int excl = base + incl - c;
        g_row[gid] = excl;
        g_cur[gid] = excl;
        g_dis[gid] = rsqrtf((float)c + 1.0f);
    }
    if (gid == 0) g_row[NN] = NE;
    gbar();

    // ---- P3: CSR scatter
    if (is64) {
        const long long* p = (const long long*)ep;
        for (int e = gid; e < NE; e += GRID * NT) {
            int s = (int)p[e];
            int d = (int)p[NE + e];
            int pos = atomicAdd(&g_cur[d], 1);
            g_csr[pos] = s;
        }
    } else {
        const int* p = (const int*)ep;
        for (int e = gid; e < NE; e += GRID * NT) {
            int s = p[e];
            int d = p[NE + e];
            int pos = atomicAdd(&g_cur[d], 1);
            g_csr[pos] = s;
        }
    }
    gbar();

    // ---- P4: layer-1 aggregation (src-scaled)  h = relu(...)
    agg1_phase(g_h1, b1, g_h);
    gbar();

    // ---- P5: layer-2 GEMM  hs2 = (h @ W2) * dis
    gemm_phase<D1, D2, true>(g_h, W2, g_hs2, sWs, sXsT, blk, GRID);
    gbar();

    // ---- P6: layer-2 aggregation  out = sigmoid(...)
    agg2_phase(g_hs2, b2, out);
}

// ---------------- launch: ONE kernel ---------------------------------------
extern "C" void kernel_launch(void* const* d_in, const int* in_sizes, int n_in,
                              void* d_out, int out_size) {
    const float* x  = (const float*)d_in[0];
    const void*  ei = d_in[1];
    const float* W1 = (const float*)d_in[2];
    const float* b1 = (const float*)d_in[3];
    const float* W2 = (const float*)d_in[4];
    const float* b2 = (const float*)d_in[5];
    float* out = (float*)d_out;

    k_fused<<<GRID, NT>>>(x, ei, W1, b1, W2, b2, out);
}

// round 12
// speedup vs baseline: 1.0460x; 1.0460x over previous
#include <cuda_runtime.h>
#include <math.h>

// Problem constants (shapes fixed by the dataset)
#define NN 50000
#define NE 800000
#define D0 64   // x features
#define D1 96   // hidden
#define D2 64   // out

#define GRID 740    // 5 blocks/SM * 148 SMs — fully balanced persistent grid
#define NT   256    // threads per block

// ---------------- scratch (device globals: no allocation allowed) ----------
__device__ int      g_is64;
__device__ int      g_csr[NE];
__device__ int      g_cnt[NN];
__device__ int      g_row[NN + 1];
__device__ int      g_cur[NN];
__device__ float    g_dis[NN];
__device__ int      g_bsum[GRID];
__device__ int      g_bpre[GRID];
__device__ unsigned g_barrier_ctr;   // monotonic across launches (replay-safe)
__device__ unsigned g_steal[4];      // work-steal counters: gemm1,agg1,gemm2,agg2
__device__ float    g_h1 [NN * D1];  // x@W1 (UNSCALED)
__device__ float    g_h  [NN * D1];  // relu(layer1)
__device__ float    g_hs2[NN * D2];  // (h@W2)*dis[row]

__device__ __forceinline__ float act_relu(float v)    { return fmaxf(v, 0.0f); }
__device__ __forceinline__ float act_sigmoid(float v) { return 1.0f / (1.0f + expf(-v)); }

// ---------------- software grid barrier ------------------------------------
// Monotonic counter, never reset: each barrier consumes exactly GRID arrivals.
__device__ __forceinline__ void gbar() {
    __threadfence();
    __syncthreads();
    if (threadIdx.x == 0) {
        unsigned old = atomicAdd(&g_barrier_ctr, 1u);
        unsigned target = (old / GRID) * GRID + GRID;
        while ((int)(*(volatile unsigned*)&g_barrier_ctr - target) < 0)
            __nanosleep(64);
        __threadfence();
    }
    __syncthreads();
}

// ---------------- GEMM phase (work-stealing tiles) --------------------------
// HS[row][c] = (SCALE ? dis[row] : 1) * sum_k X[row][k]*W[k][c].
// R10-proven inner loop. Tiles of 32 rows claimed from a global atomic
// counter -> perfect load balance; a block arriving late (longer histogram
// chunk) simply steals fewer tiles.
template <int IN, int OUT, bool SCALE>
__device__ void gemm_phase(const float* __restrict__ X, const float* __restrict__ W,
                           float* __restrict__ HS, float* sWs, float* sXs,
                           unsigned* ctr, volatile int* sSteal) {
    constexpr int CPL = OUT / 32;
    constexpr int K4  = IN / 4;
    int t = threadIdx.x;
    // stage W once (float4)
    for (int i = t; i < IN * OUT / 4; i += NT)
        ((float4*)sWs)[i] = ((const float4*)W)[i];

    int w = t >> 5, lane = t & 31;
    int rbase = w * 4;
    const int ntile = (NN + 31) / 32;

    for (;;) {
        __syncthreads();   // Ws staged / prior iter readers done with sXs+sSteal
        if (t == 0) *sSteal = (int)atomicAdd(ctr, 1u);
        __syncthreads();
        int tile = *sSteal;
        if (tile >= ntile) break;

        int row0 = tile * 32;
        for (int i = t; i < 32 * K4; i += NT) {
            int r = i / K4, k4 = i % K4;
            int gr = row0 + r;
            ((float4*)sXs)[i] = (gr < NN) ? ((const float4*)X)[gr * K4 + k4]
                                          : make_float4(0.f, 0.f, 0.f, 0.f);
        }
        __syncthreads();

        float acc[4][CPL];
#pragma unroll
        for (int r = 0; r < 4; r++)
#pragma unroll
            for (int c = 0; c < CPL; c++) acc[r][c] = 0.0f;

#pragma unroll
        for (int k = 0; k < IN; k++) {
            float wv[CPL];
#pragma unroll
            for (int c = 0; c < CPL; c++) wv[c] = sWs[k * OUT + lane + 32 * c];
            float xv[4];
#pragma unroll
            for (int r = 0; r < 4; r++) xv[r] = sXs[(rbase + r) * IN + k];
#pragma unroll
            for (int r = 0; r < 4; r++)
#pragma unroll
                for (int c = 0; c < CPL; c++)
                    acc[r][c] = fmaf(xv[r], wv[c], acc[r][c]);
        }

#pragma unroll
        for (int r = 0; r < 4; r++) {
            int gr = row0 + rbase + r;
            if (gr < NN) {
                float d = SCALE ? g_dis[gr] : 1.0f;
#pragma unroll
                for (int c = 0; c < CPL; c++)
                    HS[gr * OUT + lane + 32 * c] = SCALE ? acc[r][c] * d : acc[r][c];
            }
        }
    }
}

// ---------------- per-node aggregation bodies ------------------------------
// Layer 1 (F=96, relu, SRC-SCALED): H is UNSCALED x@W1:
//   out[i] = relu( dis_i * ( dis_i*H[i] + sum_e dis_src*H[src] ) + b )
__device__ __forceinline__ void agg1_node(int node, const float4* __restrict__ H4,
                                          const float* __restrict__ b,
                                          float* __restrict__ OUT,
                                          int lane, bool on) {
    constexpr int C4 = D1 / 4;   // 24
    int beg = g_row[node], end = g_row[node + 1];
    float di = g_dis[node];
    float4 acc = make_float4(0.f, 0.f, 0.f, 0.f);
    if (on) {
        float4 hv = H4[node * C4 + lane];          // self loop (scaled by di)
        acc.x = hv.x * di; acc.y = hv.y * di;
        acc.z = hv.z * di; acc.w = hv.w * di;
    }

    int j = beg;
    for (; j + 4 <= end; j += 4) {
        int s0 = g_csr[j + 0], s1 = g_csr[j + 1];
        int s2 = g_csr[j + 2], s3 = g_csr[j + 3];
        float d0 = g_dis[s0], d1 = g_dis[s1], d2 = g_dis[s2], d3 = g_dis[s3];
        if (on) {
            float4 v0 = H4[s0 * C4 + lane];
            float4 v1 = H4[s1 * C4 + lane];
            float4 v2 = H4[s2 * C4 + lane];
            float4 v3 = H4[s3 * C4 + lane];
            acc.x = fmaf(v0.x, d0, fmaf(v1.x, d1, fmaf(v2.x, d2, fmaf(v3.x, d3, acc.x))));
            acc.y = fmaf(v0.y, d0, fmaf(v1.y, d1, fmaf(v2.y, d2, fmaf(v3.y, d3, acc.y))));
            acc.z = fmaf(v0.z, d0, fmaf(v1.z, d1, fmaf(v2.z, d2, fmaf(v3.z, d3, acc.z))));
            acc.w = fmaf(v0.w, d0, fmaf(v1.w, d1, fmaf(v2.w, d2, fmaf(v3.w, d3, acc.w))));
        }
    }
    for (; j < end; j++) {
        int s0 = g_csr[j];
        float d0 = g_dis[s0];
        if (on) {
            float4 v = H4[s0 * C4 + lane];
            acc.x = fmaf(v.x, d0, acc.x); acc.y = fmaf(v.y, d0, acc.y);
            acc.z = fmaf(v.z, d0, acc.z); acc.w = fmaf(v.w, d0, acc.w);
        }
    }
    if (on) {
        float4 bb = ((const float4*)b)[lane];
        float4 o;
        o.x = act_relu(fmaf(di, acc.x, bb.x));
        o.y = act_relu(fmaf(di, acc.y, bb.y));
        o.z = act_relu(fmaf(di, acc.z, bb.z));
        o.w = act_relu(fmaf(di, acc.w, bb.w));
        ((float4*)OUT)[node * C4 + lane] = o;
    }
}

// Layer 2 (F=64, sigmoid): HS is PRE-SCALED (h@W2)*dis:
//   out[i] = sigmoid( dis_i * ( HS[i] + sum_e HS[src] ) + b )
__device__ __forceinline__ void agg2_node(int node, const float2* __restrict__ H2,
                                          const float* __restrict__ b,
                                          float* __restrict__ OUT, int lane) {
    constexpr int C2 = D2 / 2;   // 32
    int beg = g_row[node], end = g_row[node + 1];
    float2 acc = H2[node * C2 + lane];  // self loop

    int j = beg;
    for (; j + 4 <= end; j += 4) {
        int s0 = g_csr[j + 0], s1 = g_csr[j + 1];
        int s2 = g_csr[j + 2], s3 = g_csr[j + 3];
        float2 v0 = H2[s0 * C2 + lane];
        float2 v1 = H2[s1 * C2 + lane];
        float2 v2 = H2[s2 * C2 + lane];
        float2 v3 = H2[s3 * C2 + lane];
        acc.x += (v0.x + v1.x) + (v2.x + v3.x);
        acc.y += (v0.y + v1.y) + (v2.y + v3.y);
    }
    for (; j < end; j++) {
        int s0 = g_csr[j];
        float2 v = H2[s0 * C2 + lane];
        acc.x += v.x; acc.y += v.y;
    }
    float d = g_dis[node];
    float2 bb = ((const float2*)b)[lane];
    float2 o;
    o.x = act_sigmoid(fmaf(d, acc.x, bb.x));
    o.y = act_sigmoid(fmaf(d, acc.y, bb.y));
    ((float2*)OUT)[node * C2 + lane] = o;
}

// ---------------- the single fused persistent kernel -----------------------
// smem: sWs 24KB + sXs 12KB + scan 1KB -> ~37.3KB; 5 blocks/SM (<=51 regs).
__global__ void __launch_bounds__(NT, 5)
k_fused(const float* __restrict__ x, const void* __restrict__ ep,
        const float* __restrict__ W1, const float* __restrict__ b1,
        const float* __restrict__ W2, const float* __restrict__ b2,
        float* __restrict__ out) {
    __shared__ __align__(16) float sWs[D1 * D2 > D0 * D1 ? D1 * D2 : D0 * D1];
    __shared__ __align__(16) float sXs[32 * D1];
    __shared__ int   sScan[NT];
    __shared__ int   s_nz;
    __shared__ int   sSteal;

    int t    = threadIdx.x;
    int blk  = blockIdx.x;
    int gid  = blk * NT + t;
    int w    = t >> 5, lane = t & 31;

    // ---- P0: zero histogram; block 0 detects edge dtype; reset steal[3]
    // (used by LAST replay's P6 — kernel executions are serial, so this is
    // ordered; on the first run it is zero-init anyway).
    if (gid == 0) g_steal[3] = 0;
    if (gid < NN) g_cnt[gid] = 0;
    if (blk == 0) {
        const int* e = (const int*)ep;
        int local = 0;
#pragma unroll
        for (int q = 0; q < 4; q++) local |= e[2 * (t * 4 + q) + 1];
        if (t == 0) s_nz = 0;
        __syncthreads();
        if (local) atomicOr(&s_nz, 1);
        __syncthreads();
        if (t == 0) g_is64 = (s_nz == 0) ? 1 : 0;
    }
    gbar();
    int is64 = __ldcg(&g_is64);

    // ---- P1: in-degree histogram, then STEAL gemm1 tiles (unscaled GEMM).
    if (is64) {
        const longlong2* p = (const longlong2*)ep;
        for (int i = gid; i < NE / 2; i += GRID * NT) {
            longlong2 dd = p[NE / 2 + i];
            atomicAdd(&g_cnt[(int)dd.x], 1);
            atomicAdd(&g_cnt[(int)dd.y], 1);
        }
    } else {
        const int2* p = (const int2*)ep;
        for (int i = gid; i < NE / 2; i += GRID * NT) {
            int2 dd = p[NE / 2 + i];
            atomicAdd(&g_cnt[dd.x], 1);
            atomicAdd(&g_cnt[dd.y], 1);
        }
    }
    gemm_phase<D0, D1, false>(x, W1, g_h1, sWs, sXs, &g_steal[0], &sSteal);
    gbar();

    // ---- P2a: block-local inclusive scan of counts (one node per thread)
    int c = (gid < NN) ? __ldcg(&g_cnt[gid]) : 0;
    sScan[t] = c;
    __syncthreads();
#pragma unroll
    for (int off = 1; off < NT; off <<= 1) {
        int v = sScan[t];
        int a = (t >= off) ? sScan[t - off] : 0;
        __syncthreads();
        sScan[t] = v + a;
        __syncthreads();
    }
    int incl = sScan[t];
    if (t == NT - 1) g_bsum[blk] = incl;
    gbar();

    // ---- P2b: block 0 scans the GRID block totals (PB per thread)
    if (blk == 0) {
        constexpr int PB = (GRID + NT - 1) / NT;   // 3
        int loc[PB];
        int s = 0;
#pragma unroll
        for (int q = 0; q < PB; q++) {
            int idx = t * PB + q;
            loc[q] = (idx < GRID) ? __ldcg(&g_bsum[idx]) : 0;
            s += loc[q];
        }
        sScan[t] = s;
        __syncthreads();
#pragma unroll
        for (int off = 1; off < NT; off <<= 1) {
            int v = sScan[t];
            int ad = (t >= off) ? sScan[t - off] : 0;
            __syncthreads();
            sScan[t] = v + ad;
            __syncthreads();
        }
        int run = sScan[t] - s;   // exclusive prefix for this thread's chunk
#pragma unroll
        for (int q = 0; q < PB; q++) {
            int idx = t * PB + q;
            if (idx < GRID) { g_bpre[idx] = run; run += loc[q]; }
        }
    }
    gbar();

    // ---- P2c: write row/cur/dis; reset steal[0] (gemm1 done since P1 gbar)
    if (gid < NN) {
        int base = __ldcg(&g_bpre[blk]);
        int excl = base + incl - c;
        g_row[gid] = excl;
        g_cur[gid] = excl;
        g_dis[gid] = rsqrtf((float)c + 1.0f);
    }
    if (gid == 0) { g_row[NN] = NE; g_steal[0] = 0; }
    gbar();

    // ---- P3: CSR scatter
    if (is64) {
        const long long* p = (const long long*)ep;
        for (int e = gid; e < NE; e += GRID * NT) {
            int s = (int)p[e];
            int d = (int)p[NE + e];
            int pos = atomicAdd(&g_cur[d], 1);
            g_csr[pos] = s;
        }
    } else {
        const int* p = (const int*)ep;
        for (int e = gid; e < NE; e += GRID * NT) {
            int s = p[e];
            int d = p[NE + e];
            int pos = atomicAdd(&g_cur[d], 1);
            g_csr[pos] = s;
        }
    }
    gbar();

    // ---- P4: layer-1 aggregation, STOLEN in chunks of 16 nodes (2/warp)
    {
        const float4* H4 = (const float4*)g_h1;
        bool on = lane < (D1 / 4);
        for (;;) {
            __syncthreads();
            if (t == 0) sSteal = (int)atomicAdd(&g_steal[1], 1u);
            __syncthreads();
            int base = sSteal * 16;
            if (base >= NN) break;
#pragma unroll
            for (int q = 0; q < 2; q++) {
                int node = base + w * 2 + q;
                if (node < NN) agg1_node(node, H4, b1, g_h, lane, on);
            }
        }
    }
    gbar();

    // ---- P5: layer-2 GEMM  hs2 = (h @ W2) * dis   (stolen tiles)
    gemm_phase<D1, D2, true>(g_h, W2, g_hs2, sWs, sXs, &g_steal[2], &sSteal);
    gbar();

    // ---- P6: layer-2 aggregation (stolen); reset steal[1],[2] (quiesced)
    if (gid == 0) { g_steal[1] = 0; g_steal[2] = 0; }
    {
        const float2* H2 = (const float2*)g_hs2;
        for (;;) {
            __syncthreads();
            if (t == 0) sSteal = (int)atomicAdd(&g_steal[3], 1u);
            __syncthreads();
            int base = sSteal * 16;
            if (base >= NN) break;
#pragma unroll
            for (int q = 0; q < 2; q++) {
                int node = base + w * 2 + q;
                if (node < NN) agg2_node(node, H2, b2, out, lane);
            }
        }
    }
}

// ---------------- launch: ONE kernel ---------------------------------------
extern "C" void kernel_launch(void* const* d_in, const int* in_sizes, int n_in,
                              void* d_out, int out_size) {
    const float* x  = (const float*)d_in[0];
    const void*  ei = d_in[1];
    const float* W1 = (const float*)d_in[2];
    const float* b1 = (const float*)d_in[3];
    const float* W2 = (const float*)d_in[4];
    const float* b2 = (const float*)d_in[5];
    float* out = (float*)d_out;

    k_fused<<<GRID, NT>>>(x, ei, W1, b1, W2, b2, out);
}